// round 1
// baseline (speedup 1.0000x reference)
#include <cuda_runtime.h>

#define BB 256
#define TT 512
#define EMBD 64
#define HID 128

// Scratch (static device globals — no runtime allocation).
__device__ float g_pre1[(long)TT * BB * HID];   // [t][b][j], 64 MB
__device__ float g_h2[BB * HID];

// ---------------------------------------------------------------------------
// Kernel 1: pre1[t][b][j] = sum_k emb[x[b,t]][k] * Wih1[j][k] + b_ih1[j] + b_hh1[j]
// 512 blocks x 128 threads; thread j holds W_ih1 row j (64 floats) in registers.
// ---------------------------------------------------------------------------
__global__ __launch_bounds__(128) void k_pre1(
    const int* __restrict__ x, const float* __restrict__ emb,
    const float* __restrict__ Wih1, const float* __restrict__ bih1,
    const float* __restrict__ bhh1)
{
    __shared__ __align__(16) float shW[HID * 68];
    __shared__ __align__(16) float4 shE[8 * 16];
    __shared__ int shX[8];

    const int tid = threadIdx.x;   // 0..127 = output feature j

    // Stage W_ih1 coalesced into padded shared, then pull row into regs.
    for (int it = 0; it < 64; ++it) {
        int f = it * 128 + tid;
        int j = f >> 6, k = f & 63;
        shW[j * 68 + k] = Wih1[f];
    }
    __syncthreads();

    float Wr[64];
#pragma unroll
    for (int i = 0; i < 64; ++i) Wr[i] = shW[tid * 68 + i];
    const float bb = bih1[tid] + bhh1[tid];

    const int base = blockIdx.x * 256;              // 256 (b,t) rows per block
    const float4* __restrict__ e4 = (const float4*)emb;

    for (int it = 0; it < 32; ++it) {
        const int rid0 = base + it * 8;             // rid = t*256 + b
        if (tid < 8) {
            int rid = rid0 + tid;
            int t = rid >> 8, b = rid & 255;
            shX[tid] = x[b * TT + t];
        }
        __syncthreads();
        {
            int r = tid >> 4, f = tid & 15;
            shE[r * 16 + f] = e4[(long)shX[r] * 16 + f];
        }
        __syncthreads();

        float acc[8];
#pragma unroll
        for (int r = 0; r < 8; ++r) acc[r] = bb;
#pragma unroll
        for (int k4 = 0; k4 < 16; ++k4) {
#pragma unroll
            for (int r = 0; r < 8; ++r) {
                float4 e = shE[r * 16 + k4];
                acc[r] = fmaf(Wr[4 * k4 + 0], e.x, acc[r]);
                acc[r] = fmaf(Wr[4 * k4 + 1], e.y, acc[r]);
                acc[r] = fmaf(Wr[4 * k4 + 2], e.z, acc[r]);
                acc[r] = fmaf(Wr[4 * k4 + 3], e.w, acc[r]);
            }
        }
#pragma unroll
        for (int r = 0; r < 8; ++r)
            g_pre1[(long)(rid0 + r) * HID + tid] = acc[r];
        __syncthreads();
    }
}

// ---------------------------------------------------------------------------
// Kernel 2: fused two-layer scan. 128 blocks x 256 threads.
// Block handles batch rows b0, b0+1. Thread (j = tid&127, p = tid>>7) holds
// half-rows of W_hh1, W_ih2, W_hh2 in registers (3 x 64 floats).
//   h1 = tanh(pre1_t + W_hh1 h1)
//   h2 = tanh(W_ih2 h1 + bb2 + W_hh2 h2)
// ---------------------------------------------------------------------------
__global__ __launch_bounds__(256, 1) void k_scan(
    const float* __restrict__ Whh1, const float* __restrict__ Wih2,
    const float* __restrict__ Whh2, const float* __restrict__ bih2,
    const float* __restrict__ bhh2)
{
    __shared__ __align__(16) float sh_h1[2][HID];
    __shared__ __align__(16) float sh_h2[2][HID];
    __shared__ __align__(16) float sh_p[2][2][HID];   // [half][row][j]

    const int tid = threadIdx.x;
    const int j = tid & 127;
    const int p = tid >> 7;            // k-half: 0 or 1 (uniform per warp)
    const int b0 = blockIdx.x * 2;

    float W1r[64], Wi2r[64], W2r[64];
    {
        const float* w1 = Whh1 + j * HID + p * 64;
        const float* wi = Wih2 + j * HID + p * 64;
        const float* w2 = Whh2 + j * HID + p * 64;
#pragma unroll
        for (int i = 0; i < 64; ++i) { W1r[i] = w1[i]; Wi2r[i] = wi[i]; W2r[i] = w2[i]; }
    }
    const float bb2 = bih2[j] + bhh2[j];

    sh_h1[p][j] = 0.f;
    sh_h2[p][j] = 0.f;
    __syncthreads();

    const float* preBase = g_pre1 + (long)(b0 + p) * HID + j;
    float pre_r = preBase[0];

    for (int t = 0; t < TT; ++t) {
        // ---- Phase A: partials of W_hh1 * h1 for both rows ----
        float a0 = 0.f, a1 = 0.f;
        {
            const float4* h0p = (const float4*)&sh_h1[0][p * 64];
            const float4* h1p = (const float4*)&sh_h1[1][p * 64];
#pragma unroll
            for (int i = 0; i < 16; ++i) {
                float4 h0 = h0p[i];
                a0 = fmaf(W1r[4 * i + 0], h0.x, a0);
                a0 = fmaf(W1r[4 * i + 1], h0.y, a0);
                a0 = fmaf(W1r[4 * i + 2], h0.z, a0);
                a0 = fmaf(W1r[4 * i + 3], h0.w, a0);
                float4 h1 = h1p[i];
                a1 = fmaf(W1r[4 * i + 0], h1.x, a1);
                a1 = fmaf(W1r[4 * i + 1], h1.y, a1);
                a1 = fmaf(W1r[4 * i + 2], h1.z, a1);
                a1 = fmaf(W1r[4 * i + 3], h1.w, a1);
            }
        }
        sh_p[p][0][j] = a0;
        sh_p[p][1][j] = a1;
        __syncthreads();

        // ---- Phase B: combine + tanh; thread (j,p) is combiner for row p ----
        {
            float v = pre_r + sh_p[0][p][j] + sh_p[1][p][j];
            sh_h1[p][j] = tanhf(v);
        }
        if (t + 1 < TT) pre_r = preBase[(long)(t + 1) * BB * HID];  // prefetch
        __syncthreads();

        // ---- Phase C: partials of W_ih2*h1new + W_hh2*h2 for both rows ----
        float c0 = 0.f, c1 = 0.f, d0 = 0.f, d1 = 0.f;
        {
            const float4* h0p = (const float4*)&sh_h1[0][p * 64];
            const float4* h1p = (const float4*)&sh_h1[1][p * 64];
            const float4* g0p = (const float4*)&sh_h2[0][p * 64];
            const float4* g1p = (const float4*)&sh_h2[1][p * 64];
#pragma unroll
            for (int i = 0; i < 16; ++i) {
                float4 h0 = h0p[i];
                c0 = fmaf(Wi2r[4 * i + 0], h0.x, c0);
                c0 = fmaf(Wi2r[4 * i + 1], h0.y, c0);
                c0 = fmaf(Wi2r[4 * i + 2], h0.z, c0);
                c0 = fmaf(Wi2r[4 * i + 3], h0.w, c0);
                float4 h1 = h1p[i];
                c1 = fmaf(Wi2r[4 * i + 0], h1.x, c1);
                c1 = fmaf(Wi2r[4 * i + 1], h1.y, c1);
                c1 = fmaf(Wi2r[4 * i + 2], h1.z, c1);
                c1 = fmaf(Wi2r[4 * i + 3], h1.w, c1);
                float4 g0 = g0p[i];
                d0 = fmaf(W2r[4 * i + 0], g0.x, d0);
                d0 = fmaf(W2r[4 * i + 1], g0.y, d0);
                d0 = fmaf(W2r[4 * i + 2], g0.z, d0);
                d0 = fmaf(W2r[4 * i + 3], g0.w, d0);
                float4 g1 = g1p[i];
                d1 = fmaf(W2r[4 * i + 0], g1.x, d1);
                d1 = fmaf(W2r[4 * i + 1], g1.y, d1);
                d1 = fmaf(W2r[4 * i + 2], g1.z, d1);
                d1 = fmaf(W2r[4 * i + 3], g1.w, d1);
            }
        }
        sh_p[p][0][j] = c0 + d0;
        sh_p[p][1][j] = c1 + d1;
        __syncthreads();

        // ---- Phase D: combine + tanh for h2 ----
        {
            float v2 = bb2 + sh_p[0][p][j] + sh_p[1][p][j];
            sh_h2[p][j] = tanhf(v2);
        }
        __syncthreads();
    }

    g_h2[(b0 + p) * HID + j] = sh_h2[p][j];
}

// ---------------------------------------------------------------------------
// Kernel 3: epilogue — LN -> proj -> tanh -> LN. One block per batch row.
// ---------------------------------------------------------------------------
__global__ __launch_bounds__(128) void k_epi(
    const float* __restrict__ ln_g, const float* __restrict__ ln_b,
    const float* __restrict__ projW, const float* __restrict__ proj_b,
    const float* __restrict__ on_g, const float* __restrict__ on_b,
    float* __restrict__ out)
{
    __shared__ __align__(16) float sh_rep[HID];
    __shared__ float sh_red[8];

    const int j = threadIdx.x;
    const int b = blockIdx.x;

    float v = g_h2[b * HID + j];

    // LN 1
    float s = v, q = v * v;
#pragma unroll
    for (int o = 16; o; o >>= 1) {
        s += __shfl_xor_sync(0xffffffffu, s, o);
        q += __shfl_xor_sync(0xffffffffu, q, o);
    }
    if ((j & 31) == 0) { sh_red[j >> 5] = s; sh_red[4 + (j >> 5)] = q; }
    __syncthreads();
    s = sh_red[0] + sh_red[1] + sh_red[2] + sh_red[3];
    q = sh_red[4] + sh_red[5] + sh_red[6] + sh_red[7];
    float mu = s * (1.f / HID);
    float var = q * (1.f / HID) - mu * mu;
    float rep = (v - mu) * rsqrtf(var + 1e-5f) * ln_g[j] + ln_b[j];
    sh_rep[j] = rep;
    __syncthreads();

    // proj + tanh
    float acc = proj_b[j];
    const float4* w4 = (const float4*)(projW + j * HID);
    const float4* r4 = (const float4*)sh_rep;
#pragma unroll
    for (int i = 0; i < 32; ++i) {
        float4 w = __ldg(&w4[i]);
        float4 r = r4[i];
        acc = fmaf(w.x, r.x, acc);
        acc = fmaf(w.y, r.y, acc);
        acc = fmaf(w.z, r.z, acc);
        acc = fmaf(w.w, r.w, acc);
    }
    float tv = tanhf(acc);

    // LN 2
    __syncthreads();   // sh_red reuse
    s = tv; q = tv * tv;
#pragma unroll
    for (int o = 16; o; o >>= 1) {
        s += __shfl_xor_sync(0xffffffffu, s, o);
        q += __shfl_xor_sync(0xffffffffu, q, o);
    }
    if ((j & 31) == 0) { sh_red[j >> 5] = s; sh_red[4 + (j >> 5)] = q; }
    __syncthreads();
    s = sh_red[0] + sh_red[1] + sh_red[2] + sh_red[3];
    q = sh_red[4] + sh_red[5] + sh_red[6] + sh_red[7];
    float mu2 = s * (1.f / HID);
    float var2 = q * (1.f / HID) - mu2 * mu2;
    out[b * HID + j] = (tv - mu2) * rsqrtf(var2 + 1e-5f) * on_g[j] + on_b[j];
}

// ---------------------------------------------------------------------------
extern "C" void kernel_launch(void* const* d_in, const int* in_sizes, int n_in,
                              void* d_out, int out_size)
{
    const int*   x     = (const int*)  d_in[0];
    const float* emb   = (const float*)d_in[1];
    const float* Wih1  = (const float*)d_in[2];
    const float* bih1  = (const float*)d_in[3];
    const float* Whh1  = (const float*)d_in[4];
    const float* bhh1  = (const float*)d_in[5];
    const float* Wih2  = (const float*)d_in[6];
    const float* bih2  = (const float*)d_in[7];
    const float* Whh2  = (const float*)d_in[8];
    const float* bhh2  = (const float*)d_in[9];
    const float* ln_g  = (const float*)d_in[10];
    const float* ln_b  = (const float*)d_in[11];
    const float* projW = (const float*)d_in[12];
    const float* projb = (const float*)d_in[13];
    const float* on_g  = (const float*)d_in[14];
    const float* on_b  = (const float*)d_in[15];

    k_pre1<<<512, 128>>>(x, emb, Wih1, bih1, bhh1);
    k_scan<<<128, 256>>>(Whh1, Wih2, Whh2, bih2, bhh2);
    k_epi<<<256, 128>>>(ln_g, ln_b, projW, projb, on_g, on_b, (float*)d_out);
}